// round 16
// baseline (speedup 1.0000x reference)
#include <cuda_runtime.h>
#include <cuda_bf16.h>
#include <cstdint>

// MPSLayer: BATCH=128, two halves of 32 sites, D_BOND=128, NOUT=10.
// Basis trick -> 2304 matmuls of 128^3 on tensor cores (mma.sync m16n8k16
// bf16), 3-term bf16 hi/lo split, fp32 accumulation:
//   A*B ~= Ahi*Bhi + Alo*Bhi + Ahi*Blo
// mma computes D[m,n] = sum_k A[m,k]*Bst[n,k]; odd-tree-position outputs are
// stored TRANSPOSED by their producer. Per matrix: hi plane then lo plane.
// Tree = round-13 pair-CTA M-split + THIS ROUND: intra-level chunk-0 prefetch
// (park tile moved to stage-1; next GEMM's chunk-0 cp.async overlaps the
// epilogue stores; suppressed across pair-barrier boundaries).
// k_mat reverted to the round-11 measured optimum (4 elem/thread, z=2).

#define D      128
#define NB     128
#define NOUT   10
#define PLANE  16384
#define MAT2   32768      // hi+lo planes in bf16 elements

// ---------------- static scratch ----------------
__device__ __nv_bfloat16 g_Wc[128 * MAT2];     //   8 MB weights (odd sites transposed)
__device__ __nv_bfloat16 g_B0[128 * MAT2];     //   8 MB basis level 0
__device__ float         g_B1[256 * PLANE];    //  16 MB basis level 1 (fp32)
__device__ float         g_coef[NB * 256];     // 128 KB
__device__ __nv_bfloat16 g_M2[2048 * MAT2];    // 128 MB materialized level-1
__device__ __nv_bfloat16 g_L2[1024 * MAT2];    //  64 MB
__device__ __nv_bfloat16 g_L3[512 * MAT2];     //  32 MB
__device__ __nv_bfloat16 g_L4[256 * MAT2];     //  16 MB
__device__ int           g_sync[NB * 8];       // pair barriers (zeroed by k_init)

// ---------------- common helpers ----------------
__device__ __forceinline__ uint32_t smem_u32(const void* p) {
    uint32_t a;
    asm("{ .reg .u64 t; cvta.to.shared.u64 t, %1; cvt.u32.u64 %0, t; }" : "=r"(a) : "l"(p));
    return a;
}

#define CP_ASYNC16(dst, src) \
    asm volatile("cp.async.cg.shared.global [%0], [%1], 16;" :: "r"(dst), "l"(src))
#define CP_COMMIT()  asm volatile("cp.async.commit_group;" ::: "memory")
#define CP_WAIT(n)   asm volatile("cp.async.wait_group %0;" :: "n"(n) : "memory")

#define LDM_X4(r0, r1, r2, r3, a)                                              \
    asm volatile("ldmatrix.sync.aligned.m8n8.x4.shared.b16 {%0,%1,%2,%3}, [%4];" \
        : "=r"(r0), "=r"(r1), "=r"(r2), "=r"(r3) : "r"(a))

#define MMA_BF16(d, a, b0, b1)                                                 \
    asm volatile("mma.sync.aligned.m16n8k16.row.col.f32.bf16.bf16.f32 "        \
        "{%0,%1,%2,%3}, {%4,%5,%6,%7}, {%8,%9}, {%0,%1,%2,%3};"                \
        : "+f"((d)[0]), "+f"((d)[1]), "+f"((d)[2]), "+f"((d)[3])               \
        : "r"((a)[0]), "r"((a)[1]), "r"((a)[2]), "r"((a)[3]), "r"(b0), "r"(b1))

// ============================================================================
// 64-row half-GEMM core (round-7 proven). K=64 two upfront cp.async chunks,
// Frags register double-buffer, 144B stride, 110.6KB smem -> 2 CTAs/SM.
// ============================================================================
#define RSTRIDE  144
#define PL_A     (64 * RSTRIDE)
#define PL_B     (128 * RSTRIDE)
#define OFF_BHI  (2 * PL_A)
#define OFF_BLO  (OFF_BHI + PL_B)
#define STAGE_SM (OFF_BHI + 2 * PL_B) // 55296
#define SM_BYTES (2 * STAGE_SM)       // 110592

__device__ __forceinline__ void load_chunk64(
    uint32_t smb, int s,
    const __nv_bfloat16* __restrict__ A,
    const __nv_bfloat16* __restrict__ B,
    int c, int tid)
{
    const uint32_t stage = smb + s * STAGE_SM;
    const char* Ab = (const char*)A;
    const char* Bb = (const char*)B;
#pragma unroll
    for (int j = 0; j < 12; j++) {
        const int i = tid + j * 256;
        if (i < 1024) {
            const int p = i >> 9, idx = i & 511;
            const int r = idx >> 3, q = idx & 7;
            CP_ASYNC16(stage + p * PL_A + r * RSTRIDE + q * 16,
                       Ab + (size_t)p * (PLANE * 2) + r * 256 + c * 128 + q * 16);
        } else {
            const int i2 = i - 1024;
            const int p = i2 >> 10, idx = i2 & 1023;
            const int r = idx >> 3, q = idx & 7;
            CP_ASYNC16(stage + OFF_BHI + p * PL_B + r * RSTRIDE + q * 16,
                       Bb + (size_t)p * (PLANE * 2) + r * 256 + c * 128 + q * 16);
        }
    }
    CP_COMMIT();
}

struct Frags {
    uint32_t ah[2][4], al[2][4], bh[2][4], bl[2][4];
};

__device__ __forceinline__ void ld_frags(
    Frags& f, uint32_t st, int k16, int m0, int n0, int lr, int lk)
{
    const uint32_t kb = (uint32_t)(k16 * 32 + lk);
#pragma unroll
    for (int mt = 0; mt < 2; mt++) {
        const uint32_t ra = (uint32_t)(m0 + mt * 16 + lr) * RSTRIDE + kb;
        LDM_X4(f.ah[mt][0], f.ah[mt][1], f.ah[mt][2], f.ah[mt][3], st + ra);
        LDM_X4(f.al[mt][0], f.al[mt][1], f.al[mt][2], f.al[mt][3], st + PL_A + ra);
    }
#pragma unroll
    for (int np = 0; np < 2; np++) {
        const uint32_t rb = (uint32_t)(n0 + np * 16 + lr) * RSTRIDE + kb;
        LDM_X4(f.bh[np][0], f.bh[np][1], f.bh[np][2], f.bh[np][3], st + OFF_BHI + rb);
        LDM_X4(f.bl[np][0], f.bl[np][1], f.bl[np][2], f.bl[np][3], st + OFF_BLO + rb);
    }
}

__device__ __forceinline__ void mma_all(float acc[2][4][4], const Frags& f) {
#pragma unroll
    for (int mt = 0; mt < 2; mt++)
#pragma unroll
        for (int nt = 0; nt < 4; nt++) {
            const int g = nt >> 1, s = nt & 1;
            MMA_BF16(acc[mt][nt], f.ah[mt], f.bh[g][s], f.bh[g][s + 2]);
        }
#pragma unroll
    for (int mt = 0; mt < 2; mt++)
#pragma unroll
        for (int nt = 0; nt < 4; nt++) {
            const int g = nt >> 1, s = nt & 1;
            MMA_BF16(acc[mt][nt], f.al[mt], f.bh[g][s], f.bh[g][s + 2]);
        }
#pragma unroll
    for (int mt = 0; mt < 2; mt++)
#pragma unroll
        for (int nt = 0; nt < 4; nt++) {
            const int g = nt >> 1, s = nt & 1;
            MMA_BF16(acc[mt][nt], f.ah[mt], f.bl[g][s], f.bl[g][s + 2]);
        }
}

// ---------------------------------------------------------------------------
// Basis-kernel GEMM (round-13 verbatim): park at stage-0, no prefetch.
// mode: 0 = bf16 hi/lo store, 1 = fp32 store. transpose: store C^T half.
// ---------------------------------------------------------------------------
__device__ __forceinline__ void gemm_mma(
    const __nv_bfloat16* __restrict__ Afull,
    const __nv_bfloat16* __restrict__ B,
    float* __restrict__ Cf_g,
    __nv_bfloat16* __restrict__ Cb_g,
    int mode, int transpose, int mhalf)
{
    extern __shared__ char smem[];
    const uint32_t smb = smem_u32(smem);
    const int tid  = threadIdx.x;
    const int wid  = tid >> 5;
    const int lane = tid & 31;

    const __nv_bfloat16* A = Afull + mhalf * (64 * 128);

    const int m0 = (wid & 1) << 5;
    const int n0 = (wid >> 1) << 5;
    const int lr = lane & 15;
    const int lk = (lane >> 4) << 4;

    float acc[2][4][4];
#pragma unroll
    for (int mt = 0; mt < 2; mt++)
#pragma unroll
        for (int nt = 0; nt < 4; nt++)
#pragma unroll
            for (int q = 0; q < 4; q++) acc[mt][nt][q] = 0.0f;

    load_chunk64(smb, 0, A, B, 0, tid);
    load_chunk64(smb, 1, A, B, 1, tid);

    Frags fr[2];

#pragma unroll
    for (int c = 0; c < 2; c++) {
        if (c == 0) { CP_WAIT(1); } else { CP_WAIT(0); }
        __syncthreads();
        const uint32_t st = smb + c * STAGE_SM;

        ld_frags(fr[0], st, 0, m0, n0, lr, lk);
#pragma unroll
        for (int k16 = 0; k16 < 4; k16++) {
            const int cur = k16 & 1;
            if (k16 < 3) ld_frags(fr[cur ^ 1], st, k16 + 1, m0, n0, lr, lk);
            mma_all(acc, fr[cur]);
        }
    }

    __syncthreads();
    float* Cf = (float*)smem;     // 64 x 129 fp32 tile
    {
        const int cr = lane >> 2;
        const int cc = (lane & 3) << 1;
#pragma unroll
        for (int mt = 0; mt < 2; mt++)
#pragma unroll
            for (int nt = 0; nt < 4; nt++) {
                const int r = m0 + mt * 16 + cr;
                const int c = n0 + nt * 8 + cc;
                Cf[r * 129 + c]           = acc[mt][nt][0];
                Cf[r * 129 + c + 1]       = acc[mt][nt][1];
                Cf[(r + 8) * 129 + c]     = acc[mt][nt][2];
                Cf[(r + 8) * 129 + c + 1] = acc[mt][nt][3];
            }
    }
    __syncthreads();

    const int rbase = mhalf * 64;
    for (int i = tid; i < 4096; i += 256) {
        const int o = i << 1;
        float v0, v1;
        int e;
        if (transpose) {
            const int orow = o >> 6;
            const int ocol = o & 63;
            v0 = Cf[ocol * 129 + orow];
            v1 = Cf[(ocol + 1) * 129 + orow];
            e = orow * 128 + rbase + ocol;
        } else {
            const int r = o >> 7, c = o & 127;
            v0 = Cf[r * 129 + c];
            v1 = Cf[r * 129 + c + 1];
            e = (rbase + r) * 128 + c;
        }
        if (mode == 1) {
            *(float2*)(Cf_g + e) = make_float2(v0, v1);
        } else {
            __nv_bfloat162 hh, ll;
            hh.x = __float2bfloat16(v0);
            hh.y = __float2bfloat16(v1);
            ll.x = __float2bfloat16(v0 - __bfloat162float(hh.x));
            ll.y = __float2bfloat16(v1 - __bfloat162float(hh.y));
            *(uint32_t*)(Cb_g + e)         = *(uint32_t*)&hh;
            *(uint32_t*)(Cb_g + PLANE + e) = *(uint32_t*)&ll;
        }
    }
}

// ---------------------------------------------------------------------------
// Tree GEMM: park at STAGE-1; prefetch next GEMM's chunk-0 into stage-0
// before the epilogue stores. skip0: chunk-0 already prefetched by caller.
// store==0 -> park only (prod). Returns whether a prefetch was issued.
// ---------------------------------------------------------------------------
__device__ __forceinline__ void gemm_tree(
    const __nv_bfloat16* __restrict__ Afull,
    const __nv_bfloat16* __restrict__ B,
    __nv_bfloat16* __restrict__ Cb_g,
    int store, int transpose, int mhalf,
    const __nv_bfloat16* __restrict__ pA,   // next A (full ptr) or nullptr
    const __nv_bfloat16* __restrict__ pB,
    int skip0)
{
    extern __shared__ char smem[];
    const uint32_t smb = smem_u32(smem);
    const int tid  = threadIdx.x;
    const int wid  = tid >> 5;
    const int lane = tid & 31;

    const __nv_bfloat16* A = Afull + mhalf * (64 * 128);

    const int m0 = (wid & 1) << 5;
    const int n0 = (wid >> 1) << 5;
    const int lr = lane & 15;
    const int lk = (lane >> 4) << 4;

    float acc[2][4][4];
#pragma unroll
    for (int mt = 0; mt < 2; mt++)
#pragma unroll
        for (int nt = 0; nt < 4; nt++)
#pragma unroll
            for (int q = 0; q < 4; q++) acc[mt][nt][q] = 0.0f;

    if (!skip0) load_chunk64(smb, 0, A, B, 0, tid);
    load_chunk64(smb, 1, A, B, 1, tid);

    Frags fr[2];

#pragma unroll
    for (int c = 0; c < 2; c++) {
        if (c == 0) { CP_WAIT(1); } else { CP_WAIT(0); }
        __syncthreads();
        const uint32_t st = smb + c * STAGE_SM;

        ld_frags(fr[0], st, 0, m0, n0, lr, lk);
#pragma unroll
        for (int k16 = 0; k16 < 4; k16++) {
            const int cur = k16 & 1;
            if (k16 < 3) ld_frags(fr[cur ^ 1], st, k16 + 1, m0, n0, lr, lk);
            mma_all(acc, fr[cur]);
        }
    }

    __syncthreads();   // stage-1 reads done; stage-0 was done at top of c==1

    // prefetch next GEMM's chunk-0 into stage-0 (overlaps epilogue below)
    if (pA) load_chunk64(smb, 0, pA + mhalf * (64 * 128), pB, 0, tid);

    // park fp32 result at STAGE-1 (33KB <= 55.3KB)
    float* Cf = (float*)(smem + STAGE_SM);
    {
        const int cr = lane >> 2;
        const int cc = (lane & 3) << 1;
#pragma unroll
        for (int mt = 0; mt < 2; mt++)
#pragma unroll
            for (int nt = 0; nt < 4; nt++) {
                const int r = m0 + mt * 16 + cr;
                const int c = n0 + nt * 8 + cc;
                Cf[r * 129 + c]           = acc[mt][nt][0];
                Cf[r * 129 + c + 1]       = acc[mt][nt][1];
                Cf[(r + 8) * 129 + c]     = acc[mt][nt][2];
                Cf[(r + 8) * 129 + c + 1] = acc[mt][nt][3];
            }
    }
    __syncthreads();

    if (!store) return;   // parked (prod step)

    const int rbase = mhalf * 64;
    for (int i = tid; i < 4096; i += 256) {
        const int o = i << 1;
        float v0, v1;
        int e;
        if (transpose) {
            const int orow = o >> 6;
            const int ocol = o & 63;
            v0 = Cf[ocol * 129 + orow];
            v1 = Cf[(ocol + 1) * 129 + orow];
            e = orow * 128 + rbase + ocol;
        } else {
            const int r = o >> 7, c = o & 127;
            v0 = Cf[r * 129 + c];
            v1 = Cf[r * 129 + c + 1];
            e = (rbase + r) * 128 + c;
        }
        __nv_bfloat162 hh, ll;
        hh.x = __float2bfloat16(v0);
        hh.y = __float2bfloat16(v1);
        ll.x = __float2bfloat16(v0 - __bfloat162float(hh.x));
        ll.y = __float2bfloat16(v1 - __bfloat162float(hh.y));
        *(uint32_t*)(Cb_g + e)         = *(uint32_t*)&hh;
        *(uint32_t*)(Cb_g + PLANE + e) = *(uint32_t*)&ll;
    }
}

// ============================================================================
// Level kernels
// ============================================================================

// Fused weight-convert + coefficient kernel; also zeroes g_sync and out.
__global__ __launch_bounds__(256)
void k_init(const float* __restrict__ inputs,
            const float* __restrict__ left, const float* __restrict__ right,
            float* __restrict__ out) {
    const int blk = blockIdx.x;
    if (blk < 128) {
        if (blk == 0) {
            for (int i = threadIdx.x; i < NB * 8; i += 256) g_sync[i] = 0;
            for (int i = threadIdx.x; i < NB * NOUT; i += 256) out[i] = 0.0f;
        }
        const int m = blk;
        const int h = m >> 6;
        const int s = (m >> 5) & 1;
        const int site = m & 31;
        const float* src = (h ? right : left) + (size_t)(s * 32 + site) * PLANE;
        __nv_bfloat16* dst = g_Wc + (size_t)m * MAT2;
        const bool tr = site & 1;
        for (int e = threadIdx.x; e < PLANE; e += 256) {
            const float v = tr ? src[(e & 127) * 128 + (e >> 7)] : src[e];
            const __nv_bfloat16 hi = __float2bfloat16(v);
            dst[e] = hi;
            dst[PLANE + e] = __float2bfloat16(v - __bfloat162float(hi));
        }
    } else {
        const int b = blk - 128;
        const int tid = threadIdx.x;
        const int h = tid >> 7, q = (tid >> 4) & 7, t = tid & 15;
        const int base = h * 32 + q * 4;
        const float c = inputs[(b * 64 + base + 0) * 2 + ((t >> 3) & 1)]
                      * inputs[(b * 64 + base + 1) * 2 + ((t >> 2) & 1)]
                      * inputs[(b * 64 + base + 2) * 2 + ((t >> 1) & 1)]
                      * inputs[(b * 64 + base + 3) * 2 + (t & 1)];
        g_coef[b * 256 + tid] = c;
    }
}

__global__ __launch_bounds__(256, 2)
void k_basis0() {
    const int mh = blockIdx.x & 1;
    const int m = blockIdx.x >> 1;
    const int h = m >> 6, p = (m >> 2) & 15, a = m & 3;
    const int s0 = a >> 1, s1 = a & 1;
    gemm_mma(g_Wc + (size_t)(h * 64 + s0 * 32 + 2 * p) * MAT2,
             g_Wc + (size_t)(h * 64 + s1 * 32 + 2 * p + 1) * MAT2,
             nullptr, g_B0 + (size_t)m * MAT2, 0, p & 1, mh);
}

__global__ __launch_bounds__(256, 2)
void k_basis1() {
    const int mh = blockIdx.x & 1;
    const int m = blockIdx.x >> 1;
    const int h = m >> 7, q = (m >> 4) & 7, t = m & 15;
    const int a = t >> 2, b = t & 3;
    gemm_mma(g_B0 + (size_t)((h * 16 + 2 * q) * 4 + a) * MAT2,
             g_B0 + (size_t)((h * 16 + 2 * q + 1) * 4 + b) * MAT2,
             g_B1 + (size_t)m * PLANE, nullptr, 1, q & 1, mh);
}

// Materialize M2[b,hq] = sum_t coef * B1[hq,t]; hi/lo bf16 out.
// Round-11 optimum: f32x2, 4 elems/thread, 64 batches/block, grid (16,16,2).
__global__ __launch_bounds__(256)
void k_mat() {
    const int hq = blockIdx.y;
    const int b0 = blockIdx.z << 6;
    const int e  = (blockIdx.x * 256 + threadIdx.x) * 4;

    __shared__ unsigned long long scp[64][16];
    for (int i = threadIdx.x; i < 64 * 16; i += 256) {
        const uint32_t cu = __float_as_uint(
            g_coef[(b0 + (i >> 4)) * 256 + hq * 16 + (i & 15)]);
        scp[i >> 4][i & 15] = ((unsigned long long)cu << 32) | cu;
    }
    __syncthreads();

    ulonglong2 v[16];
    const float* src = g_B1 + (size_t)hq * 16 * PLANE + e;
#pragma unroll
    for (int t = 0; t < 16; t++) v[t] = *(const ulonglong2*)(src + (size_t)t * PLANE);

    for (int bb = 0; bb < 64; bb++) {
        unsigned long long s01 = 0ull, s23 = 0ull;
#pragma unroll
        for (int t = 0; t < 16; t++) {
            const unsigned long long c2 = scp[bb][t];
            asm("fma.rn.f32x2 %0, %1, %2, %0;" : "+l"(s01) : "l"(c2), "l"(v[t].x));
            asm("fma.rn.f32x2 %0, %1, %2, %0;" : "+l"(s23) : "l"(c2), "l"(v[t].y));
        }
        const float s0 = __uint_as_float((uint32_t)s01);
        const float s1 = __uint_as_float((uint32_t)(s01 >> 32));
        const float s2 = __uint_as_float((uint32_t)s23);
        const float s3 = __uint_as_float((uint32_t)(s23 >> 32));
        __nv_bfloat162 h0 = __float22bfloat162_rn(make_float2(s0, s1));
        __nv_bfloat162 h1 = __float22bfloat162_rn(make_float2(s2, s3));
        float2 f0 = __bfloat1622float2(h0);
        float2 f1 = __bfloat1622float2(h1);
        __nv_bfloat162 l0 = __float22bfloat162_rn(make_float2(s0 - f0.x, s1 - f0.y));
        __nv_bfloat162 l1 = __float22bfloat162_rn(make_float2(s2 - f1.x, s3 - f1.y));
        __nv_bfloat16* dst = g_M2 + (size_t)((b0 + bb) * 16 + hq) * MAT2 + e;
        *(uint2*)dst = make_uint2(*(uint32_t*)&h0, *(uint32_t*)&h1);
        *(uint2*)(dst + PLANE) = make_uint2(*(uint32_t*)&l0, *(uint32_t*)&l1);
    }
}

// ============================================================================
// Pair-CTA fused tree with intra-level chunk-0 prefetch. grid = 256 (b, mh).
// Steps: 0..7 l2, 8..11 l3, 12..13 l4, 14 prod. Barriers after 7, 11, 13.
// ============================================================================
__device__ __forceinline__ void step_ptrs(
    int b, int s,
    const __nv_bfloat16*& A, const __nv_bfloat16*& Bm,
    __nv_bfloat16*& outp, int& tr, int& store)
{
    if (s < 8) {
        const int h = s >> 2, r = s & 3;
        A = g_M2 + (size_t)(b * 16 + h * 8 + 2 * r) * MAT2;
        Bm = A + MAT2;
        outp = g_L2 + (size_t)(b * 8 + h * 4 + r) * MAT2;
        tr = r & 1; store = 1;
    } else if (s < 12) {
        const int t = s - 8, h = t >> 1, r = t & 1;
        A = g_L2 + (size_t)(b * 8 + h * 4 + 2 * r) * MAT2;
        Bm = A + MAT2;
        outp = g_L3 + (size_t)(b * 4 + h * 2 + r) * MAT2;
        tr = r & 1; store = 1;
    } else if (s < 14) {
        const int h = s - 12;
        A = g_L3 + (size_t)(b * 4 + h * 2) * MAT2;
        Bm = A + MAT2;
        outp = g_L4 + (size_t)(b * 2 + h) * MAT2;
        tr = (h == 0); store = 1;
    } else {
        A = g_L4 + (size_t)(b * 2 + 1) * MAT2;   // R
        Bm = g_L4 + (size_t)(b * 2 + 0) * MAT2;  // L (stored transposed)
        outp = nullptr; tr = 0; store = 0;
    }
}

__device__ __forceinline__ void pair_barrier(int b, int phase) {
    __syncthreads();
    __threadfence();
    if (threadIdx.x == 0) {
        atomicAdd(&g_sync[b * 8 + phase], 1);
        while (*(volatile int*)&g_sync[b * 8 + phase] < 2) { }
    }
    __syncthreads();
    __threadfence();
}

__global__ __launch_bounds__(256, 2)
void k_tree(const float* __restrict__ middle, float* __restrict__ out) {
    extern __shared__ char smem[];
    const int tid = threadIdx.x;
    const int mh = blockIdx.x & 1;
    const int b  = blockIdx.x >> 1;

    int skip0 = 0;
#pragma unroll 1
    for (int s = 0; s < 15; s++) {
        const __nv_bfloat16 *A, *Bm;
        __nv_bfloat16* outp;
        int tr, store;
        step_ptrs(b, s, A, Bm, outp, tr, store);

        // prefetch next step's chunk-0 only within a level (no barrier cross)
        const __nv_bfloat16 *pA = nullptr, *pB = nullptr;
        if (s != 7 && s != 11 && s != 13 && s != 14) {
            __nv_bfloat16* o2; int t2, st2;
            step_ptrs(b, s + 1, pA, pB, o2, t2, st2);
        }

        gemm_tree(A, Bm, outp, store, tr, mh, pA, pB, skip0);
        skip0 = (pA != nullptr);
        __syncthreads();

        if (s == 7)  pair_barrier(b, 0);
        if (s == 11) pair_barrier(b, 1);
        if (s == 13) pair_barrier(b, 2);
    }

    // trace partial: out[b,c] += sum_{j, k in half} middle[c,j,k] * P[k,j]
    // P's 64-row half parked at STAGE-1.
    const float* Cf = (const float*)(smem + STAGE_SM);
    const int kbase = mh * 64;
    float part[NOUT];
#pragma unroll
    for (int c = 0; c < NOUT; c++) part[c] = 0.0f;

    for (int e = tid; e < 8192; e += 256) {
        const int r = e & 63, j = e >> 6;
        const float p = Cf[r * 129 + j];
        const int k = kbase + r;
#pragma unroll
        for (int c = 0; c < NOUT; c++)
            part[c] = fmaf(middle[c * PLANE + j * 128 + k], p, part[c]);
    }

    __shared__ float red[256];
#pragma unroll
    for (int c = 0; c < NOUT; c++) {
        red[tid] = part[c];
        __syncthreads();
        for (int s = 128; s > 0; s >>= 1) {
            if (tid < s) red[tid] += red[tid + s];
            __syncthreads();
        }
        if (tid == 0) atomicAdd(&out[b * NOUT + c], red[0]);
        __syncthreads();
    }
}

// ============================================================================
extern "C" void kernel_launch(void* const* d_in, const int* in_sizes, int n_in,
                              void* d_out, int out_size) {
    const float* inputs = (const float*)d_in[0];  // (128, 64, 2)
    const float* left   = (const float*)d_in[1];  // (2, 32, 128, 128)
    const float* right  = (const float*)d_in[2];  // (2, 32, 128, 128)
    const float* middle = (const float*)d_in[3];  // (10, 128, 128)
    float* out = (float*)d_out;                   // (128, 10)

    cudaFuncSetAttribute(k_basis0, cudaFuncAttributeMaxDynamicSharedMemorySize, SM_BYTES);
    cudaFuncSetAttribute(k_basis1, cudaFuncAttributeMaxDynamicSharedMemorySize, SM_BYTES);
    cudaFuncSetAttribute(k_tree,   cudaFuncAttributeMaxDynamicSharedMemorySize, SM_BYTES);

    k_init  <<<256, 256>>>(inputs, left, right, out);
    k_basis0<<<256, 256, SM_BYTES>>>();
    k_basis1<<<512, 256, SM_BYTES>>>();
    k_mat   <<<dim3(16, 16, 2), 256>>>();
    k_tree  <<<256, 256, SM_BYTES>>>(middle, out);
}

// round 17
// speedup vs baseline: 1.0515x; 1.0515x over previous
#include <cuda_runtime.h>
#include <cuda_bf16.h>
#include <cstdint>

// MPSLayer: BATCH=128, two halves of 32 sites, D_BOND=128, NOUT=10.
// Basis trick -> 2304 matmuls of 128^3 on tensor cores (mma.sync m16n8k16
// bf16), 3-term bf16 hi/lo split, fp32 accumulation:
//   A*B ~= Ahi*Bhi + Alo*Bhi + Ahi*Blo
// mma computes D[m,n] = sum_k A[m,k]*Bst[n,k]; odd-tree-position outputs are
// stored TRANSPOSED by their producer. Per matrix: hi plane then lo plane.
// Tree = round-13 measured optimum (pair-CTA M-split, 3 pair barriers,
// NO prefetch). k_mat = round-11 blocking (4 elem/thread, 64 batches, z=2)
// + THIS ROUND: even/odd-t split accumulator chains (depth 16 -> 8).

#define D      128
#define NB     128
#define NOUT   10
#define PLANE  16384
#define MAT2   32768      // hi+lo planes in bf16 elements

// ---------------- static scratch ----------------
__device__ __nv_bfloat16 g_Wc[128 * MAT2];     //   8 MB weights (odd sites transposed)
__device__ __nv_bfloat16 g_B0[128 * MAT2];     //   8 MB basis level 0
__device__ float         g_B1[256 * PLANE];    //  16 MB basis level 1 (fp32)
__device__ float         g_coef[NB * 256];     // 128 KB
__device__ __nv_bfloat16 g_M2[2048 * MAT2];    // 128 MB materialized level-1
__device__ __nv_bfloat16 g_L2[1024 * MAT2];    //  64 MB
__device__ __nv_bfloat16 g_L3[512 * MAT2];     //  32 MB
__device__ __nv_bfloat16 g_L4[256 * MAT2];     //  16 MB
__device__ int           g_sync[NB * 8];       // pair barriers (zeroed by k_init)

// ---------------- common helpers ----------------
__device__ __forceinline__ uint32_t smem_u32(const void* p) {
    uint32_t a;
    asm("{ .reg .u64 t; cvta.to.shared.u64 t, %1; cvt.u32.u64 %0, t; }" : "=r"(a) : "l"(p));
    return a;
}

#define CP_ASYNC16(dst, src) \
    asm volatile("cp.async.cg.shared.global [%0], [%1], 16;" :: "r"(dst), "l"(src))
#define CP_COMMIT()  asm volatile("cp.async.commit_group;" ::: "memory")
#define CP_WAIT(n)   asm volatile("cp.async.wait_group %0;" :: "n"(n) : "memory")

#define LDM_X4(r0, r1, r2, r3, a)                                              \
    asm volatile("ldmatrix.sync.aligned.m8n8.x4.shared.b16 {%0,%1,%2,%3}, [%4];" \
        : "=r"(r0), "=r"(r1), "=r"(r2), "=r"(r3) : "r"(a))

#define MMA_BF16(d, a, b0, b1)                                                 \
    asm volatile("mma.sync.aligned.m16n8k16.row.col.f32.bf16.bf16.f32 "        \
        "{%0,%1,%2,%3}, {%4,%5,%6,%7}, {%8,%9}, {%0,%1,%2,%3};"                \
        : "+f"((d)[0]), "+f"((d)[1]), "+f"((d)[2]), "+f"((d)[3])               \
        : "r"((a)[0]), "r"((a)[1]), "r"((a)[2]), "r"((a)[3]), "r"(b0), "r"(b1))

// ============================================================================
// 64-row half-GEMM core (round-7 proven). K=64 two upfront cp.async chunks,
// Frags register double-buffer, 144B stride, 110.6KB smem -> 2 CTAs/SM.
// ============================================================================
#define RSTRIDE  144
#define PL_A     (64 * RSTRIDE)
#define PL_B     (128 * RSTRIDE)
#define OFF_BHI  (2 * PL_A)
#define OFF_BLO  (OFF_BHI + PL_B)
#define STAGE_SM (OFF_BHI + 2 * PL_B) // 55296
#define SM_BYTES (2 * STAGE_SM)       // 110592

__device__ __forceinline__ void load_chunk64(
    uint32_t smb, int s,
    const __nv_bfloat16* __restrict__ A,
    const __nv_bfloat16* __restrict__ B,
    int c, int tid)
{
    const uint32_t stage = smb + s * STAGE_SM;
    const char* Ab = (const char*)A;
    const char* Bb = (const char*)B;
#pragma unroll
    for (int j = 0; j < 12; j++) {
        const int i = tid + j * 256;
        if (i < 1024) {
            const int p = i >> 9, idx = i & 511;
            const int r = idx >> 3, q = idx & 7;
            CP_ASYNC16(stage + p * PL_A + r * RSTRIDE + q * 16,
                       Ab + (size_t)p * (PLANE * 2) + r * 256 + c * 128 + q * 16);
        } else {
            const int i2 = i - 1024;
            const int p = i2 >> 10, idx = i2 & 1023;
            const int r = idx >> 3, q = idx & 7;
            CP_ASYNC16(stage + OFF_BHI + p * PL_B + r * RSTRIDE + q * 16,
                       Bb + (size_t)p * (PLANE * 2) + r * 256 + c * 128 + q * 16);
        }
    }
    CP_COMMIT();
}

struct Frags {
    uint32_t ah[2][4], al[2][4], bh[2][4], bl[2][4];
};

__device__ __forceinline__ void ld_frags(
    Frags& f, uint32_t st, int k16, int m0, int n0, int lr, int lk)
{
    const uint32_t kb = (uint32_t)(k16 * 32 + lk);
#pragma unroll
    for (int mt = 0; mt < 2; mt++) {
        const uint32_t ra = (uint32_t)(m0 + mt * 16 + lr) * RSTRIDE + kb;
        LDM_X4(f.ah[mt][0], f.ah[mt][1], f.ah[mt][2], f.ah[mt][3], st + ra);
        LDM_X4(f.al[mt][0], f.al[mt][1], f.al[mt][2], f.al[mt][3], st + PL_A + ra);
    }
#pragma unroll
    for (int np = 0; np < 2; np++) {
        const uint32_t rb = (uint32_t)(n0 + np * 16 + lr) * RSTRIDE + kb;
        LDM_X4(f.bh[np][0], f.bh[np][1], f.bh[np][2], f.bh[np][3], st + OFF_BHI + rb);
        LDM_X4(f.bl[np][0], f.bl[np][1], f.bl[np][2], f.bl[np][3], st + OFF_BLO + rb);
    }
}

__device__ __forceinline__ void mma_all(float acc[2][4][4], const Frags& f) {
#pragma unroll
    for (int mt = 0; mt < 2; mt++)
#pragma unroll
        for (int nt = 0; nt < 4; nt++) {
            const int g = nt >> 1, s = nt & 1;
            MMA_BF16(acc[mt][nt], f.ah[mt], f.bh[g][s], f.bh[g][s + 2]);
        }
#pragma unroll
    for (int mt = 0; mt < 2; mt++)
#pragma unroll
        for (int nt = 0; nt < 4; nt++) {
            const int g = nt >> 1, s = nt & 1;
            MMA_BF16(acc[mt][nt], f.al[mt], f.bh[g][s], f.bh[g][s + 2]);
        }
#pragma unroll
    for (int mt = 0; mt < 2; mt++)
#pragma unroll
        for (int nt = 0; nt < 4; nt++) {
            const int g = nt >> 1, s = nt & 1;
            MMA_BF16(acc[mt][nt], f.ah[mt], f.bl[g][s], f.bl[g][s + 2]);
        }
}

// mode: 0 = bf16 hi/lo store, 1 = fp32 store, 2 = park only (leave fp32
// 64x129 tile at smem base). transpose: store C^T half.
__device__ __forceinline__ void gemm_mma(
    const __nv_bfloat16* __restrict__ Afull,
    const __nv_bfloat16* __restrict__ B,
    float* __restrict__ Cf_g,
    __nv_bfloat16* __restrict__ Cb_g,
    int mode, int transpose, int mhalf)
{
    extern __shared__ char smem[];
    const uint32_t smb = smem_u32(smem);
    const int tid  = threadIdx.x;
    const int wid  = tid >> 5;
    const int lane = tid & 31;

    const __nv_bfloat16* A = Afull + mhalf * (64 * 128);

    const int m0 = (wid & 1) << 5;
    const int n0 = (wid >> 1) << 5;
    const int lr = lane & 15;
    const int lk = (lane >> 4) << 4;

    float acc[2][4][4];
#pragma unroll
    for (int mt = 0; mt < 2; mt++)
#pragma unroll
        for (int nt = 0; nt < 4; nt++)
#pragma unroll
            for (int q = 0; q < 4; q++) acc[mt][nt][q] = 0.0f;

    load_chunk64(smb, 0, A, B, 0, tid);
    load_chunk64(smb, 1, A, B, 1, tid);

    Frags fr[2];

#pragma unroll
    for (int c = 0; c < 2; c++) {
        if (c == 0) { CP_WAIT(1); } else { CP_WAIT(0); }
        __syncthreads();
        const uint32_t st = smb + c * STAGE_SM;

        ld_frags(fr[0], st, 0, m0, n0, lr, lk);
#pragma unroll
        for (int k16 = 0; k16 < 4; k16++) {
            const int cur = k16 & 1;
            if (k16 < 3) ld_frags(fr[cur ^ 1], st, k16 + 1, m0, n0, lr, lk);
            mma_all(acc, fr[cur]);
        }
    }

    __syncthreads();
    float* Cf = (float*)smem;     // 64 x 129 fp32 tile
    {
        const int cr = lane >> 2;
        const int cc = (lane & 3) << 1;
#pragma unroll
        for (int mt = 0; mt < 2; mt++)
#pragma unroll
            for (int nt = 0; nt < 4; nt++) {
                const int r = m0 + mt * 16 + cr;
                const int c = n0 + nt * 8 + cc;
                Cf[r * 129 + c]           = acc[mt][nt][0];
                Cf[r * 129 + c + 1]       = acc[mt][nt][1];
                Cf[(r + 8) * 129 + c]     = acc[mt][nt][2];
                Cf[(r + 8) * 129 + c + 1] = acc[mt][nt][3];
            }
    }
    __syncthreads();

    if (mode == 2) return;        // parked

    const int rbase = mhalf * 64;
    for (int i = tid; i < 4096; i += 256) {
        const int o = i << 1;
        float v0, v1;
        int e;
        if (transpose) {
            const int orow = o >> 6;
            const int ocol = o & 63;
            v0 = Cf[ocol * 129 + orow];
            v1 = Cf[(ocol + 1) * 129 + orow];
            e = orow * 128 + rbase + ocol;
        } else {
            const int r = o >> 7, c = o & 127;
            v0 = Cf[r * 129 + c];
            v1 = Cf[r * 129 + c + 1];
            e = (rbase + r) * 128 + c;
        }
        if (mode == 1) {
            *(float2*)(Cf_g + e) = make_float2(v0, v1);
        } else {
            __nv_bfloat162 hh, ll;
            hh.x = __float2bfloat16(v0);
            hh.y = __float2bfloat16(v1);
            ll.x = __float2bfloat16(v0 - __bfloat162float(hh.x));
            ll.y = __float2bfloat16(v1 - __bfloat162float(hh.y));
            *(uint32_t*)(Cb_g + e)         = *(uint32_t*)&hh;
            *(uint32_t*)(Cb_g + PLANE + e) = *(uint32_t*)&ll;
        }
    }
}

// ============================================================================
// Level kernels
// ============================================================================

// Fused weight-convert + coefficient kernel; also zeroes g_sync and out.
__global__ __launch_bounds__(256)
void k_init(const float* __restrict__ inputs,
            const float* __restrict__ left, const float* __restrict__ right,
            float* __restrict__ out) {
    const int blk = blockIdx.x;
    if (blk < 128) {
        if (blk == 0) {
            for (int i = threadIdx.x; i < NB * 8; i += 256) g_sync[i] = 0;
            for (int i = threadIdx.x; i < NB * NOUT; i += 256) out[i] = 0.0f;
        }
        const int m = blk;
        const int h = m >> 6;
        const int s = (m >> 5) & 1;
        const int site = m & 31;
        const float* src = (h ? right : left) + (size_t)(s * 32 + site) * PLANE;
        __nv_bfloat16* dst = g_Wc + (size_t)m * MAT2;
        const bool tr = site & 1;
        for (int e = threadIdx.x; e < PLANE; e += 256) {
            const float v = tr ? src[(e & 127) * 128 + (e >> 7)] : src[e];
            const __nv_bfloat16 hi = __float2bfloat16(v);
            dst[e] = hi;
            dst[PLANE + e] = __float2bfloat16(v - __bfloat162float(hi));
        }
    } else {
        const int b = blk - 128;
        const int tid = threadIdx.x;
        const int h = tid >> 7, q = (tid >> 4) & 7, t = tid & 15;
        const int base = h * 32 + q * 4;
        const float c = inputs[(b * 64 + base + 0) * 2 + ((t >> 3) & 1)]
                      * inputs[(b * 64 + base + 1) * 2 + ((t >> 2) & 1)]
                      * inputs[(b * 64 + base + 2) * 2 + ((t >> 1) & 1)]
                      * inputs[(b * 64 + base + 3) * 2 + (t & 1)];
        g_coef[b * 256 + tid] = c;
    }
}

__global__ __launch_bounds__(256, 2)
void k_basis0() {
    const int mh = blockIdx.x & 1;
    const int m = blockIdx.x >> 1;
    const int h = m >> 6, p = (m >> 2) & 15, a = m & 3;
    const int s0 = a >> 1, s1 = a & 1;
    gemm_mma(g_Wc + (size_t)(h * 64 + s0 * 32 + 2 * p) * MAT2,
             g_Wc + (size_t)(h * 64 + s1 * 32 + 2 * p + 1) * MAT2,
             nullptr, g_B0 + (size_t)m * MAT2, 0, p & 1, mh);
}

__global__ __launch_bounds__(256, 2)
void k_basis1() {
    const int mh = blockIdx.x & 1;
    const int m = blockIdx.x >> 1;
    const int h = m >> 7, q = (m >> 4) & 7, t = m & 15;
    const int a = t >> 2, b = t & 3;
    gemm_mma(g_B0 + (size_t)((h * 16 + 2 * q) * 4 + a) * MAT2,
             g_B0 + (size_t)((h * 16 + 2 * q + 1) * 4 + b) * MAT2,
             g_B1 + (size_t)m * PLANE, nullptr, 1, q & 1, mh);
}

// Materialize M2[b,hq] = sum_t coef * B1[hq,t]; hi/lo bf16 out.
// Round-11 blocking (f32x2, 4 elems/thread, 64 batches/block, grid (16,16,2))
// + even/odd-t SPLIT ACCUMULATOR CHAINS (depth 16 -> 8, 2x ILP).
__global__ __launch_bounds__(256)
void k_mat() {
    const int hq = blockIdx.y;
    const int b0 = blockIdx.z << 6;
    const int e  = (blockIdx.x * 256 + threadIdx.x) * 4;

    __shared__ unsigned long long scp[64][16];
    for (int i = threadIdx.x; i < 64 * 16; i += 256) {
        const uint32_t cu = __float_as_uint(
            g_coef[(b0 + (i >> 4)) * 256 + hq * 16 + (i & 15)]);
        scp[i >> 4][i & 15] = ((unsigned long long)cu << 32) | cu;
    }
    __syncthreads();

    ulonglong2 v[16];
    const float* src = g_B1 + (size_t)hq * 16 * PLANE + e;
#pragma unroll
    for (int t = 0; t < 16; t++) v[t] = *(const ulonglong2*)(src + (size_t)t * PLANE);

    for (int bb = 0; bb < 64; bb++) {
        unsigned long long sa01 = 0ull, sb01 = 0ull;   // even-t / odd-t chains
        unsigned long long sa23 = 0ull, sb23 = 0ull;
#pragma unroll
        for (int t = 0; t < 16; t += 2) {
            const unsigned long long c0 = scp[bb][t];
            const unsigned long long c1 = scp[bb][t + 1];
            asm("fma.rn.f32x2 %0, %1, %2, %0;" : "+l"(sa01) : "l"(c0), "l"(v[t].x));
            asm("fma.rn.f32x2 %0, %1, %2, %0;" : "+l"(sa23) : "l"(c0), "l"(v[t].y));
            asm("fma.rn.f32x2 %0, %1, %2, %0;" : "+l"(sb01) : "l"(c1), "l"(v[t + 1].x));
            asm("fma.rn.f32x2 %0, %1, %2, %0;" : "+l"(sb23) : "l"(c1), "l"(v[t + 1].y));
        }
        unsigned long long s01, s23;
        asm("add.rn.f32x2 %0, %1, %2;" : "=l"(s01) : "l"(sa01), "l"(sb01));
        asm("add.rn.f32x2 %0, %1, %2;" : "=l"(s23) : "l"(sa23), "l"(sb23));
        const float s0 = __uint_as_float((uint32_t)s01);
        const float s1 = __uint_as_float((uint32_t)(s01 >> 32));
        const float s2 = __uint_as_float((uint32_t)s23);
        const float s3 = __uint_as_float((uint32_t)(s23 >> 32));
        __nv_bfloat162 h0 = __float22bfloat162_rn(make_float2(s0, s1));
        __nv_bfloat162 h1 = __float22bfloat162_rn(make_float2(s2, s3));
        float2 f0 = __bfloat1622float2(h0);
        float2 f1 = __bfloat1622float2(h1);
        __nv_bfloat162 l0 = __float22bfloat162_rn(make_float2(s0 - f0.x, s1 - f0.y));
        __nv_bfloat162 l1 = __float22bfloat162_rn(make_float2(s2 - f1.x, s3 - f1.y));
        __nv_bfloat16* dst = g_M2 + (size_t)((b0 + bb) * 16 + hq) * MAT2 + e;
        *(uint2*)dst = make_uint2(*(uint32_t*)&h0, *(uint32_t*)&h1);
        *(uint2*)(dst + PLANE) = make_uint2(*(uint32_t*)&l0, *(uint32_t*)&l1);
    }
}

// ============================================================================
// Pair-CTA fused tree (round-13 optimum, verbatim). grid = 256: CTA (b, mh).
// 3 pair barriers at level boundaries; trace partials + atomicAdd.
// ============================================================================
__device__ __forceinline__ void pair_barrier(int b, int phase) {
    __syncthreads();
    __threadfence();
    if (threadIdx.x == 0) {
        atomicAdd(&g_sync[b * 8 + phase], 1);
        while (*(volatile int*)&g_sync[b * 8 + phase] < 2) { }
    }
    __syncthreads();
    __threadfence();
}

__global__ __launch_bounds__(256, 2)
void k_tree(const float* __restrict__ middle, float* __restrict__ out) {
    extern __shared__ char smem[];
    const int tid = threadIdx.x;
    const int mh = blockIdx.x & 1;
    const int b  = blockIdx.x >> 1;

    // l2: 8 GEMMs (this CTA does rows mh*64..+63 of each)
#pragma unroll 1
    for (int s = 0; s < 8; s++) {
        const int h = s >> 2, r = s & 3;
        const __nv_bfloat16* A = g_M2 + (size_t)(b * 16 + h * 8 + 2 * r) * MAT2;
        gemm_mma(A, A + MAT2, nullptr,
                 g_L2 + (size_t)(b * 8 + h * 4 + r) * MAT2, 0, r & 1, mh);
        __syncthreads();
    }
    pair_barrier(b, 0);

    // l3: 4 GEMMs
#pragma unroll 1
    for (int s = 0; s < 4; s++) {
        const int h = s >> 1, r = s & 1;
        const __nv_bfloat16* A = g_L2 + (size_t)(b * 8 + h * 4 + 2 * r) * MAT2;
        gemm_mma(A, A + MAT2, nullptr,
                 g_L3 + (size_t)(b * 4 + h * 2 + r) * MAT2, 0, r & 1, mh);
        __syncthreads();
    }
    pair_barrier(b, 1);

    // l4: 2 GEMMs. L (h=0) stored transposed (B-operand of prod).
#pragma unroll 1
    for (int h = 0; h < 2; h++) {
        const __nv_bfloat16* A = g_L3 + (size_t)(b * 4 + h * 2) * MAT2;
        gemm_mma(A, A + MAT2, nullptr,
                 g_L4 + (size_t)(b * 2 + h) * MAT2, 0, h == 0, mh);
        __syncthreads();
    }
    pair_barrier(b, 2);

    // prod: P = R @ L, park this CTA's 64-row half in smem
    gemm_mma(g_L4 + (size_t)(b * 2 + 1) * MAT2,
             g_L4 + (size_t)(b * 2 + 0) * MAT2,
             nullptr, nullptr, 2, 0, mh);

    // trace partial: out[b,c] += sum_{j, k in half} middle[c,j,k] * P[k,j]
    const float* Cf = (const float*)smem;   // local row r = global k - mh*64
    const int kbase = mh * 64;
    float part[NOUT];
#pragma unroll
    for (int c = 0; c < NOUT; c++) part[c] = 0.0f;

    for (int e = tid; e < 8192; e += 256) {
        const int r = e & 63, j = e >> 6;
        const float p = Cf[r * 129 + j];
        const int k = kbase + r;
#pragma unroll
        for (int c = 0; c < NOUT; c++)
            part[c] = fmaf(middle[c * PLANE + j * 128 + k], p, part[c]);
    }

    __shared__ float red[256];
#pragma unroll
    for (int c = 0; c < NOUT; c++) {
        red[tid] = part[c];
        __syncthreads();
        for (int s = 128; s > 0; s >>= 1) {
            if (tid < s) red[tid] += red[tid + s];
            __syncthreads();
        }
        if (tid == 0) atomicAdd(&out[b * NOUT + c], red[0]);
        __syncthreads();
    }
}

// ============================================================================
extern "C" void kernel_launch(void* const* d_in, const int* in_sizes, int n_in,
                              void* d_out, int out_size) {
    const float* inputs = (const float*)d_in[0];  // (128, 64, 2)
    const float* left   = (const float*)d_in[1];  // (2, 32, 128, 128)
    const float* right  = (const float*)d_in[2];  // (2, 32, 128, 128)
    const float* middle = (const float*)d_in[3];  // (10, 128, 128)
    float* out = (float*)d_out;                   // (128, 10)

    cudaFuncSetAttribute(k_basis0, cudaFuncAttributeMaxDynamicSharedMemorySize, SM_BYTES);
    cudaFuncSetAttribute(k_basis1, cudaFuncAttributeMaxDynamicSharedMemorySize, SM_BYTES);
    cudaFuncSetAttribute(k_tree,   cudaFuncAttributeMaxDynamicSharedMemorySize, SM_BYTES);

    k_init  <<<256, 256>>>(inputs, left, right, out);
    k_basis0<<<256, 256, SM_BYTES>>>();
    k_basis1<<<512, 256, SM_BYTES>>>();
    k_mat   <<<dim3(16, 16, 2), 256>>>();
    k_tree  <<<256, 256, SM_BYTES>>>(middle, out);
}